// round 14
// baseline (speedup 1.0000x reference)
#include <cuda_runtime.h>
#include <cuda_bf16.h>
#include <cstdint>

#define NN 50000
#define EE 800000
#define H  128
constexpr float BN_EPS = 1e-5f;
constexpr float SLOPE  = 0.01f;

// ---------------- scratch (device globals; no allocation allowed) ----------
// packed (bf16 hi | bf16 lo<<16) feature buffers
__device__ __align__(16) unsigned g_xP  [NN * H];
__device__ __align__(16) unsigned g_hA  [NN * H];
__device__ __align__(16) unsigned g_hB  [NN * H];
__device__ __align__(16) unsigned g_aggP[NN * H];
__device__ __align__(16) unsigned g_WtP [4 * H * 256];  // W^T packed, all layers
__device__ __align__(16) unsigned g_yP  [NN * H];       // packed pre-BN activations
__device__ int      g_rowptr[NN + 1];
__device__ int      g_cursor[NN];
__device__ int      g_col[EE];
__device__ int      g_bsum[256];
__device__ int      g_boff[256];
__device__ float    g_sum[4 * H];
__device__ float    g_sumsq[4 * H];
__device__ float    g_scale[H];
__device__ float    g_shift[H];
__device__ unsigned g_scnt[4];
__device__ int      g_is64;

// ---------------- helpers --------------------------------------------------
__device__ __forceinline__ const unsigned* pickP(int s) {
    return (s == 0) ? (const unsigned*)g_xP
         : (s == 1) ? (const unsigned*)g_hA : (const unsigned*)g_hB;
}
__device__ __forceinline__ unsigned* pickPw(int s) {
    return (s == 1) ? (unsigned*)g_hA : (unsigned*)g_hB;
}

__device__ __forceinline__ unsigned pack_f32(float v) {
    unsigned hb = (unsigned)__bfloat16_as_ushort(__float2bfloat16(v));
    float hf = __uint_as_float(hb << 16);
    float r = v - hf;
    unsigned lb = (unsigned)__bfloat16_as_ushort(__float2bfloat16(r));
    return hb | (lb << 16);
}
__device__ __forceinline__ float unpack_f32(unsigned p) {
    return __uint_as_float(p << 16) + __uint_as_float(p & 0xFFFF0000u);
}

__device__ __forceinline__ uint32_t smem_to_u32(const void* p) {
    uint32_t a;
    asm("{ .reg .u64 t; cvta.to.shared.u64 t, %1; cvt.u32.u64 %0, t; }"
        : "=r"(a) : "l"(p));
    return a;
}

// ldmatrix x4 (baseline PTX, legal on compute_103)
__device__ __forceinline__ void ldm_x4(uint32_t* f, uint32_t addr) {
    asm volatile("ldmatrix.sync.aligned.m8n8.x4.shared.b16 {%0,%1,%2,%3}, [%4];"
                 : "=r"(f[0]), "=r"(f[1]), "=r"(f[2]), "=r"(f[3]) : "r"(addr));
}
// mma m16n8k16 bf16 (baseline PTX, sm_80+)
__device__ __forceinline__ void mma_bf16(float* c, const uint32_t* a, const uint32_t* b) {
    asm volatile("mma.sync.aligned.m16n8k16.row.col.f32.bf16.bf16.f32 "
                 "{%0,%1,%2,%3}, {%4,%5,%6,%7}, {%8,%9}, {%0,%1,%2,%3};"
                 : "+f"(c[0]), "+f"(c[1]), "+f"(c[2]), "+f"(c[3])
                 : "r"(a[0]), "r"(a[1]), "r"(a[2]), "r"(a[3]),
                   "r"(b[0]), "r"(b[1]));
}

// edge accessors honoring detected dtype
__device__ __forceinline__ int edge_src(const void* ei, int e) {
    if (g_is64) return (int)((const long long*)ei)[e];
    return ((const int*)ei)[e];
}
__device__ __forceinline__ int edge_dst(const void* ei, int e) {
    if (g_is64) return (int)((const long long*)ei)[EE + e];
    return ((const int*)ei)[EE + e];
}

// ---------------- CSR build ------------------------------------------------
// block 0 additionally probes the edge dtype (int64 vs int32)
__global__ void k_zero_deg(const void* ei) {
    int i = blockIdx.x * blockDim.x + threadIdx.x;
    if (i < NN) g_cursor[i] = 0;
    if (blockIdx.x == 0) {
        __shared__ int bad;
        if (threadIdx.x == 0) bad = 0;
        __syncthreads();
        long long v = ((const long long*)ei)[threadIdx.x];
        if (v < 0 || v >= NN) atomicOr(&bad, 1);
        __syncthreads();
        if (threadIdx.x == 0) g_is64 = bad ? 0 : 1;
    }
}
__global__ void k_hist(const void* __restrict__ ei) {
    int e = blockIdx.x * blockDim.x + threadIdx.x;
    if (e < EE) atomicAdd(&g_cursor[edge_dst(ei, e)], 1);
}
__global__ void k_scan1() {
    __shared__ int s[256];
    int t = threadIdx.x, i = blockIdx.x * 256 + t;
    int d = (i < NN) ? g_cursor[i] : 0;
    s[t] = d;
    __syncthreads();
    for (int off = 1; off < 256; off <<= 1) {
        int add = (t >= off) ? s[t - off] : 0;
        __syncthreads();
        s[t] += add;
        __syncthreads();
    }
    if (i < NN) g_rowptr[i] = s[t] - d;
    if (t == 255) g_bsum[blockIdx.x] = s[255];
}
__global__ void k_scan2() {
    __shared__ int s[256];
    int t = threadIdx.x;
    int d = (t < 196) ? g_bsum[t] : 0;
    s[t] = d;
    __syncthreads();
    for (int off = 1; off < 256; off <<= 1) {
        int add = (t >= off) ? s[t - off] : 0;
        __syncthreads();
        s[t] += add;
        __syncthreads();
    }
    if (t < 196) g_boff[t] = s[t] - d;
}
__global__ void k_scan3() {
    int i = blockIdx.x * 256 + threadIdx.x;
    if (i < NN) {
        int v = g_rowptr[i] + g_boff[blockIdx.x];
        g_rowptr[i] = v;
        g_cursor[i] = v;
    }
    if (i == 0) g_rowptr[NN] = EE;
}
__global__ void k_fill(const void* __restrict__ ei) {
    int e = blockIdx.x * blockDim.x + threadIdx.x;
    if (e < EE) {
        int src = edge_src(ei, e);
        int pos = atomicAdd(&g_cursor[edge_dst(ei, e)], 1);
        g_col[pos] = src;
    }
}

// ---------------- input / weight packing -----------------------------------
__global__ void k_xprep(const float* __restrict__ x) {
    int i = blockIdx.x * blockDim.x + threadIdx.x;
    if (i < NN * H) g_xP[i] = pack_f32(x[i]);
}
// ALL layers' W^T packed upfront (B[n][k] = Wcat[k][n]); zeroes all BN stats
__global__ void k_wprep_all(const float* __restrict__ Wl,
                            const float* __restrict__ Wr) {
    int b = blockIdx.x;              // 0..511
    int l = b >> 7;                  // layer 0..3
    int idx = (b & 127) * 256 + threadIdx.x;   // 0..32767
    int n = idx >> 8, k = idx & 255;
    const float* wl = Wl + l * H * H;
    const float* wr = Wr + l * H * H;
    float w = (k < H) ? wl[k * H + n] : wr[(k - H) * H + n];
    g_WtP[l * (H * 256) + n * 256 + k] = pack_f32(w);
    if ((b & 127) == 0 && threadIdx.x < H) {
        g_sum[l * H + threadIdx.x]   = 0.f;
        g_sumsq[l * H + threadIdx.x] = 0.f;
        if (b == 0 && threadIdx.x < 4) g_scnt[threadIdx.x] = 0u;
    }
}

// ---------------- aggregation: one warp per node, 4-wide edge unroll -------
__global__ void __launch_bounds__(256) k_agg(int src) {
    int warp = threadIdx.x >> 5;
    int lane = threadIdx.x & 31;
    int node = blockIdx.x * 8 + warp;
    if (node >= NN) return;
    const uint4* in4 = (const uint4*)pickP(src);
    int beg = g_rowptr[node];
    int end = g_rowptr[node + 1];
    float4 a = make_float4(0.f, 0.f, 0.f, 0.f);
    int j = beg;
    for (; j + 3 < end; j += 4) {
        int s0 = g_col[j + 0], s1 = g_col[j + 1];
        int s2 = g_col[j + 2], s3 = g_col[j + 3];
        uint4 w0 = in4[s0 * 32 + lane];
        uint4 w1 = in4[s1 * 32 + lane];
        uint4 w2 = in4[s2 * 32 + lane];
        uint4 w3 = in4[s3 * 32 + lane];
        a.x += (unpack_f32(w0.x) + unpack_f32(w1.x)) + (unpack_f32(w2.x) + unpack_f32(w3.x));
        a.y += (unpack_f32(w0.y) + unpack_f32(w1.y)) + (unpack_f32(w2.y) + unpack_f32(w3.y));
        a.z += (unpack_f32(w0.z) + unpack_f32(w1.z)) + (unpack_f32(w2.z) + unpack_f32(w3.z));
        a.w += (unpack_f32(w0.w) + unpack_f32(w1.w)) + (unpack_f32(w2.w) + unpack_f32(w3.w));
    }
    for (; j < end; j++) {
        uint4 w0 = in4[g_col[j] * 32 + lane];
        a.x += unpack_f32(w0.x); a.y += unpack_f32(w0.y);
        a.z += unpack_f32(w0.z); a.w += unpack_f32(w0.w);
    }
    float inv = 1.0f / (float)max(end - beg, 1);
    uint4 o = make_uint4(pack_f32(a.x * inv), pack_f32(a.y * inv),
                         pack_f32(a.z * inv), pack_f32(a.w * inv));
    ((uint4*)g_aggP)[node * 32 + lane] = o;
}

// ---------------- tensor-core GEMM (mma.sync bf16, 3-term split) -----------
// D[128,128] fp32 = sum over K=256 of Ah@Bh + Ah@Bl + Al@Bh
// A = [agg | h], B = W^T[n][k] (per-layer slice). Epilogue -> packed g_yP.
// smem tiles: 128 rows x 64 bf16, row stride 144B (ldmatrix conflict-free).
// __launch_bounds__(256,2): 2 CTAs/SM (proven round 13).
// EXPERIMENT (this round): epilogue stores PACKED y (uint2) instead of fp32 —
// halves y write traffic; stats/bn unpack on read. Transient pack temps only.
#define SA_STRIDE 144
#define TILE_BYTES (128 * SA_STRIDE)           // 18432
#define GEMM_SMEM  (4 * TILE_BYTES)            // 73728

__device__ __forceinline__ void load_split_tile(
    uint32_t sm_hi, uint32_t sm_lo,
    const unsigned* __restrict__ src, int row0, int stride, int col0,
    int tid, int rows_valid)
{
    int r = tid >> 1;
    int h = (tid & 1) * 32;
    bool valid = r < rows_valid;
    const uint4* p4 = (const uint4*)(src + (size_t)(row0 + r) * stride + col0 + h);
    #pragma unroll
    for (int u = 0; u < 8; u++) {
        uint4 w = valid ? p4[u] : make_uint4(0u, 0u, 0u, 0u);
        unsigned h01 = __byte_perm(w.x, w.y, 0x5410);   // hi bf16 pair
        unsigned h23 = __byte_perm(w.z, w.w, 0x5410);
        unsigned l01 = __byte_perm(w.x, w.y, 0x7632);   // lo bf16 pair
        unsigned l23 = __byte_perm(w.z, w.w, 0x7632);
        uint32_t off = (uint32_t)(r * SA_STRIDE + (h + u * 4) * 2);
        asm volatile("st.shared.v2.b32 [%0], {%1,%2};"
                     :: "r"(sm_hi + off), "r"(h01), "r"(h23) : "memory");
        asm volatile("st.shared.v2.b32 [%0], {%1,%2};"
                     :: "r"(sm_lo + off), "r"(l01), "r"(l23) : "memory");
    }
}

__global__ void __launch_bounds__(256, 2) k_gemm(int src, int layer,
                                                 const float* __restrict__ bias) {
    extern __shared__ char smem[];
    uint32_t sAh = smem_to_u32(smem);
    uint32_t sAl = sAh + TILE_BYTES;
    uint32_t sBh = sAh + 2 * TILE_BYTES;
    uint32_t sBl = sAh + 3 * TILE_BYTES;

    const int tid  = threadIdx.x;
    const int lane = tid & 31;
    const int wid  = tid >> 5;
    const int wm   = wid >> 1;       // 0..3  (m: 32 rows each)
    const int wn   = wid & 1;        // 0..1  (n: 64 cols each)
    const int row0 = blockIdx.x * 128;
    const unsigned* hsrc = pickP(src);
    const unsigned* wsrc = g_WtP + layer * (H * 256);

    int arows = NN - row0;
    if (arows > 128) arows = 128;

    float acc[2][8][4];
    #pragma unroll
    for (int i = 0; i < 2; i++)
        #pragma unroll
        for (int j = 0; j < 8; j++)
            #pragma unroll
            for (int q = 0; q < 4; q++) acc[i][j][q] = 0.f;

    const int lrow = lane & 15;
    const int lchk = lane >> 4;

    for (int c = 0; c < 4; c++) {
        const unsigned* asrc = (c < 2) ? (const unsigned*)g_aggP : hsrc;
        int acol = (c & 1) * 64;
        load_split_tile(sAh, sAl, asrc, row0, 128, acol, tid, arows);
        load_split_tile(sBh, sBl, wsrc, 0, 256, c * 64, tid, 128);
        __syncthreads();

        #pragma unroll
        for (int ks = 0; ks < 4; ks++) {
            uint32_t Ah[2][4], Al[2][4];
            #pragma unroll
            for (int im = 0; im < 2; im++) {
                uint32_t aoff = (uint32_t)((wm * 32 + im * 16 + lrow) * SA_STRIDE
                                           + (ks * 16 + lchk * 8) * 2);
                ldm_x4(Ah[im], sAh + aoff);
                ldm_x4(Al[im], sAl + aoff);
            }
            uint32_t Bh[8][2], Bl[8][2];
            #pragma unroll
            for (int jn = 0; jn < 4; jn++) {
                uint32_t boff = (uint32_t)((wn * 64 + jn * 16 + lrow) * SA_STRIDE
                                           + (ks * 16 + lchk * 8) * 2);
                uint32_t t[4];
                ldm_x4(t, sBh + boff);
                Bh[2 * jn][0] = t[0]; Bh[2 * jn][1] = t[2];
                Bh[2 * jn + 1][0] = t[1]; Bh[2 * jn + 1][1] = t[3];
                ldm_x4(t, sBl + boff);
                Bl[2 * jn][0] = t[0]; Bl[2 * jn][1] = t[2];
                Bl[2 * jn + 1][0] = t[1]; Bl[2 * jn + 1][1] = t[3];
            }
            #pragma unroll
            for (int im = 0; im < 2; im++)
                #pragma unroll
                for (int j = 0; j < 8; j++)
                    mma_bf16(acc[im][j], Ah[im], Bh[j]);
            #pragma unroll
            for (int im = 0; im < 2; im++)
                #pragma unroll
                for (int j = 0; j < 8; j++)
                    mma_bf16(acc[im][j], Ah[im], Bl[j]);
            #pragma unroll
            for (int im = 0; im < 2; im++)
                #pragma unroll
                for (int j = 0; j < 8; j++)
                    mma_bf16(acc[im][j], Al[im], Bh[j]);
        }
        __syncthreads();
    }

    // epilogue: bias + leaky relu -> packed g_yP
    const int lr  = lane >> 2;
    const int lc2 = (lane & 3) * 2;
    #pragma unroll
    for (int im = 0; im < 2; im++) {
        #pragma unroll
        for (int j = 0; j < 8; j++) {
            int n = wn * 64 + j * 8 + lc2;
            float b0 = bias[n], b1 = bias[n + 1];
            int m0 = row0 + wm * 32 + im * 16 + lr;
            if (m0 < NN) {
                float v0 = acc[im][j][0] + b0;
                float v1 = acc[im][j][1] + b1;
                v0 = (v0 >= 0.f) ? v0 : SLOPE * v0;
                v1 = (v1 >= 0.f) ? v1 : SLOPE * v1;
                *(uint2*)&g_yP[(size_t)m0 * H + n] =
                    make_uint2(pack_f32(v0), pack_f32(v1));
            }
            int m1 = m0 + 8;
            if (m1 < NN) {
                float v2 = acc[im][j][2] + b0;
                float v3 = acc[im][j][3] + b1;
                v2 = (v2 >= 0.f) ? v2 : SLOPE * v2;
                v3 = (v3 >= 0.f) ? v3 : SLOPE * v3;
                *(uint2*)&g_yP[(size_t)m1 * H + n] =
                    make_uint2(pack_f32(v2), pack_f32(v3));
            }
        }
    }
}

// ---------------- BN stats (+ fused bnprep in last block) -------------------
__global__ void k_stats(int l, const float* __restrict__ gamma,
                        const float* __restrict__ beta) {
    int t = threadIdx.x;            // 128 threads = columns
    int r0 = blockIdx.x * 250;      // 200 blocks x 250 rows
    float s = 0.f, q = 0.f;
    for (int r = 0; r < 250; r++) {
        float v = unpack_f32(g_yP[(size_t)(r0 + r) * H + t]);
        s += v;
        q += v * v;
    }
    atomicAdd(&g_sum[l * H + t], s);
    atomicAdd(&g_sumsq[l * H + t], q);
    __threadfence();
    __shared__ int isLast;
    if (t == 0) {
        unsigned old = atomicInc(&g_scnt[l], 199u);   // wraps to 0 after last
        isLast = (old == 199u);
    }
    __syncthreads();
    if (isLast) {
        float sum = atomicAdd(&g_sum[l * H + t], 0.f);
        float ssq = atomicAdd(&g_sumsq[l * H + t], 0.f);
        float inv_n = 1.0f / (float)NN;
        float mu  = sum * inv_n;
        float var = ssq * inv_n - mu * mu;
        float sc  = rsqrtf(var + BN_EPS) * gamma[t];
        g_scale[t] = sc;
        g_shift[t] = beta[t] - mu * sc;
    }
}
// BN apply: packed g_yP -> packed h buffer dst (intermediate layers),
//           or packed g_yP -> fp32 dout only (final layer)
__global__ void k_bn(int dst, float* __restrict__ dout) {
    int i = blockIdx.x * blockDim.x + threadIdx.x;
    if (i < NN * 32) {
        int c = (i & 31) * 4;
        uint4 p = ((const uint4*)g_yP)[i];
        float4 v;
        v.x = unpack_f32(p.x) * g_scale[c + 0] + g_shift[c + 0];
        v.y = unpack_f32(p.y) * g_scale[c + 1] + g_shift[c + 1];
        v.z = unpack_f32(p.z) * g_scale[c + 2] + g_shift[c + 2];
        v.w = unpack_f32(p.w) * g_scale[c + 3] + g_shift[c + 3];
        if (dout) {
            ((float4*)dout)[i] = v;
        } else {
            uint4 o = make_uint4(pack_f32(v.x), pack_f32(v.y),
                                 pack_f32(v.z), pack_f32(v.w));
            ((uint4*)pickPw(dst))[i] = o;
        }
    }
}

// ---------------- launch ---------------------------------------------------
extern "C" void kernel_launch(void* const* d_in, const int* in_sizes, int n_in,
                              void* d_out, int out_size) {
    const float* x     = (const float*)d_in[0];
    const void*  ei    = d_in[1];
    const float* Wl    = (const float*)d_in[2];
    const float* bl    = (const float*)d_in[3];
    const float* Wr    = (const float*)d_in[4];
    const float* gamma = (const float*)d_in[5];
    const float* beta  = (const float*)d_in[6];
    float*       out   = (float*)d_out;

    cudaFuncSetAttribute(k_gemm, cudaFuncAttributeMaxDynamicSharedMemorySize, GEMM_SMEM);

    // input pack + CSR build + all-layer weight pack
    k_xprep    <<<(NN * H + 255) / 256, 256>>>(x);
    k_zero_deg <<<196, 256>>>(ei);
    k_hist     <<<(EE + 255) / 256, 256>>>(ei);
    k_scan1    <<<196, 256>>>();
    k_scan2    <<<1, 256>>>();
    k_scan3    <<<196, 256>>>();
    k_fill     <<<(EE + 255) / 256, 256>>>(ei);
    k_wprep_all<<<512, 256>>>(Wl, Wr);

    // l0: xP->A, l1: A->B, l2: B->A, l3: A -> d_out
    const int srcs[4] = {0, 1, 2, 1};
    const int dsts[4] = {1, 2, 1, 2};

    for (int l = 0; l < 4; l++) {
        k_agg  <<<(NN + 7) / 8, 256>>>(srcs[l]);
        k_gemm <<<(NN + 127) / 128, 256, GEMM_SMEM>>>(srcs[l], l, bl + l * H);
        k_stats<<<200, 128>>>(l, gamma + l * H, beta + l * H);
        k_bn   <<<(NN * 32 + 255) / 256, 256>>>(dsts[l], (l == 3) ? out : nullptr);
    }
}

// round 15
// speedup vs baseline: 1.0264x; 1.0264x over previous
#include <cuda_runtime.h>
#include <cuda_bf16.h>
#include <cstdint>

#define NN 50000
#define EE 800000
#define H  128
constexpr float BN_EPS = 1e-5f;
constexpr float SLOPE  = 0.01f;

// ---------------- scratch (device globals; no allocation allowed) ----------
// packed (bf16 hi | bf16 lo<<16) feature buffers
__device__ __align__(16) unsigned g_xP  [NN * H];
__device__ __align__(16) unsigned g_hA  [NN * H];
__device__ __align__(16) unsigned g_hB  [NN * H];
__device__ __align__(16) unsigned g_aggP[NN * H];
__device__ __align__(16) unsigned g_WtP [4 * H * 256];  // W^T packed, all layers
__device__ __align__(16) float    g_y   [NN * H];       // fp32 pre-BN activations
__device__ int      g_rowptr[NN + 1];
__device__ int      g_cursor[NN];
__device__ int      g_col[EE];
__device__ int      g_bsum[256];
__device__ int      g_boff[256];
__device__ float    g_sum[4 * H];
__device__ float    g_sumsq[4 * H];
__device__ float    g_scale[H];
__device__ float    g_shift[H];
__device__ unsigned g_scnt[4];
__device__ int      g_is64;

// ---------------- helpers --------------------------------------------------
__device__ __forceinline__ const unsigned* pickP(int s) {
    return (s == 0) ? (const unsigned*)g_xP
         : (s == 1) ? (const unsigned*)g_hA : (const unsigned*)g_hB;
}
__device__ __forceinline__ unsigned* pickPw(int s) {
    return (s == 1) ? (unsigned*)g_hA : (unsigned*)g_hB;
}

__device__ __forceinline__ unsigned pack_f32(float v) {
    unsigned hb = (unsigned)__bfloat16_as_ushort(__float2bfloat16(v));
    float hf = __uint_as_float(hb << 16);
    float r = v - hf;
    unsigned lb = (unsigned)__bfloat16_as_ushort(__float2bfloat16(r));
    return hb | (lb << 16);
}
__device__ __forceinline__ float unpack_f32(unsigned p) {
    return __uint_as_float(p << 16) + __uint_as_float(p & 0xFFFF0000u);
}

__device__ __forceinline__ uint32_t smem_to_u32(const void* p) {
    uint32_t a;
    asm("{ .reg .u64 t; cvta.to.shared.u64 t, %1; cvt.u32.u64 %0, t; }"
        : "=r"(a) : "l"(p));
    return a;
}

// ldmatrix x4 (baseline PTX, legal on compute_103)
__device__ __forceinline__ void ldm_x4(uint32_t* f, uint32_t addr) {
    asm volatile("ldmatrix.sync.aligned.m8n8.x4.shared.b16 {%0,%1,%2,%3}, [%4];"
                 : "=r"(f[0]), "=r"(f[1]), "=r"(f[2]), "=r"(f[3]) : "r"(addr));
}
// mma m16n8k16 bf16 (baseline PTX, sm_80+)
__device__ __forceinline__ void mma_bf16(float* c, const uint32_t* a, const uint32_t* b) {
    asm volatile("mma.sync.aligned.m16n8k16.row.col.f32.bf16.bf16.f32 "
                 "{%0,%1,%2,%3}, {%4,%5,%6,%7}, {%8,%9}, {%0,%1,%2,%3};"
                 : "+f"(c[0]), "+f"(c[1]), "+f"(c[2]), "+f"(c[3])
                 : "r"(a[0]), "r"(a[1]), "r"(a[2]), "r"(a[3]),
                   "r"(b[0]), "r"(b[1]));
}

// edge accessors honoring detected dtype
__device__ __forceinline__ int edge_src(const void* ei, int e) {
    if (g_is64) return (int)((const long long*)ei)[e];
    return ((const int*)ei)[e];
}
__device__ __forceinline__ int edge_dst(const void* ei, int e) {
    if (g_is64) return (int)((const long long*)ei)[EE + e];
    return ((const int*)ei)[EE + e];
}

// ---------------- CSR build ------------------------------------------------
// block 0 additionally probes the edge dtype (int64 vs int32)
__global__ void k_zero_deg(const void* ei) {
    int i = blockIdx.x * blockDim.x + threadIdx.x;
    if (i < NN) g_cursor[i] = 0;
    if (blockIdx.x == 0) {
        __shared__ int bad;
        if (threadIdx.x == 0) bad = 0;
        __syncthreads();
        long long v = ((const long long*)ei)[threadIdx.x];
        if (v < 0 || v >= NN) atomicOr(&bad, 1);
        __syncthreads();
        if (threadIdx.x == 0) g_is64 = bad ? 0 : 1;
    }
}
__global__ void k_hist(const void* __restrict__ ei) {
    int e = blockIdx.x * blockDim.x + threadIdx.x;
    if (e < EE) atomicAdd(&g_cursor[edge_dst(ei, e)], 1);
}
__global__ void k_scan1() {
    __shared__ int s[256];
    int t = threadIdx.x, i = blockIdx.x * 256 + t;
    int d = (i < NN) ? g_cursor[i] : 0;
    s[t] = d;
    __syncthreads();
    for (int off = 1; off < 256; off <<= 1) {
        int add = (t >= off) ? s[t - off] : 0;
        __syncthreads();
        s[t] += add;
        __syncthreads();
    }
    if (i < NN) g_rowptr[i] = s[t] - d;
    if (t == 255) g_bsum[blockIdx.x] = s[255];
}
__global__ void k_scan2() {
    __shared__ int s[256];
    int t = threadIdx.x;
    int d = (t < 196) ? g_bsum[t] : 0;
    s[t] = d;
    __syncthreads();
    for (int off = 1; off < 256; off <<= 1) {
        int add = (t >= off) ? s[t - off] : 0;
        __syncthreads();
        s[t] += add;
        __syncthreads();
    }
    if (t < 196) g_boff[t] = s[t] - d;
}
__global__ void k_scan3() {
    int i = blockIdx.x * 256 + threadIdx.x;
    if (i < NN) {
        int v = g_rowptr[i] + g_boff[blockIdx.x];
        g_rowptr[i] = v;
        g_cursor[i] = v;
    }
    if (i == 0) g_rowptr[NN] = EE;
}
__global__ void k_fill(const void* __restrict__ ei) {
    int e = blockIdx.x * blockDim.x + threadIdx.x;
    if (e < EE) {
        int src = edge_src(ei, e);
        int pos = atomicAdd(&g_cursor[edge_dst(ei, e)], 1);
        g_col[pos] = src;
    }
}

// ---------------- input / weight packing -----------------------------------
__global__ void k_xprep(const float* __restrict__ x) {
    int i = blockIdx.x * blockDim.x + threadIdx.x;
    if (i < NN * H) g_xP[i] = pack_f32(x[i]);
}
// ALL layers' W^T packed upfront (B[n][k] = Wcat[k][n]); zeroes all BN stats
__global__ void k_wprep_all(const float* __restrict__ Wl,
                            const float* __restrict__ Wr) {
    int b = blockIdx.x;              // 0..511
    int l = b >> 7;                  // layer 0..3
    int idx = (b & 127) * 256 + threadIdx.x;   // 0..32767
    int n = idx >> 8, k = idx & 255;
    const float* wl = Wl + l * H * H;
    const float* wr = Wr + l * H * H;
    float w = (k < H) ? wl[k * H + n] : wr[(k - H) * H + n];
    g_WtP[l * (H * 256) + n * 256 + k] = pack_f32(w);
    if ((b & 127) == 0 && threadIdx.x < H) {
        g_sum[l * H + threadIdx.x]   = 0.f;
        g_sumsq[l * H + threadIdx.x] = 0.f;
        if (b == 0 && threadIdx.x < 4) g_scnt[threadIdx.x] = 0u;
    }
}

// ---------------- aggregation: one warp per node, 4-wide edge unroll -------
__global__ void __launch_bounds__(256) k_agg(int src) {
    int warp = threadIdx.x >> 5;
    int lane = threadIdx.x & 31;
    int node = blockIdx.x * 8 + warp;
    if (node >= NN) return;
    const uint4* in4 = (const uint4*)pickP(src);
    int beg = g_rowptr[node];
    int end = g_rowptr[node + 1];
    float4 a = make_float4(0.f, 0.f, 0.f, 0.f);
    int j = beg;
    for (; j + 3 < end; j += 4) {
        int s0 = g_col[j + 0], s1 = g_col[j + 1];
        int s2 = g_col[j + 2], s3 = g_col[j + 3];
        uint4 w0 = in4[s0 * 32 + lane];
        uint4 w1 = in4[s1 * 32 + lane];
        uint4 w2 = in4[s2 * 32 + lane];
        uint4 w3 = in4[s3 * 32 + lane];
        a.x += (unpack_f32(w0.x) + unpack_f32(w1.x)) + (unpack_f32(w2.x) + unpack_f32(w3.x));
        a.y += (unpack_f32(w0.y) + unpack_f32(w1.y)) + (unpack_f32(w2.y) + unpack_f32(w3.y));
        a.z += (unpack_f32(w0.z) + unpack_f32(w1.z)) + (unpack_f32(w2.z) + unpack_f32(w3.z));
        a.w += (unpack_f32(w0.w) + unpack_f32(w1.w)) + (unpack_f32(w2.w) + unpack_f32(w3.w));
    }
    for (; j < end; j++) {
        uint4 w0 = in4[g_col[j] * 32 + lane];
        a.x += unpack_f32(w0.x); a.y += unpack_f32(w0.y);
        a.z += unpack_f32(w0.z); a.w += unpack_f32(w0.w);
    }
    float inv = 1.0f / (float)max(end - beg, 1);
    uint4 o = make_uint4(pack_f32(a.x * inv), pack_f32(a.y * inv),
                         pack_f32(a.z * inv), pack_f32(a.w * inv));
    ((uint4*)g_aggP)[node * 32 + lane] = o;
}

// ---------------- tensor-core GEMM (mma.sync bf16, 3-term split) -----------
// D[128,128] fp32 = sum over K=256 of Ah@Bh + Ah@Bl + Al@Bh
// A = [agg | h], B = W^T[n][k] (per-layer slice). Epilogue -> g_y (fp32).
// smem tiles: 128 rows x 64 bf16, row stride 144B (ldmatrix conflict-free).
// __launch_bounds__(256,2): 2 CTAs/SM (proven round 13). Epilogue minimal —
// every attempted addition (stats atomics, packing) has measurably regressed.
#define SA_STRIDE 144
#define TILE_BYTES (128 * SA_STRIDE)           // 18432
#define GEMM_SMEM  (4 * TILE_BYTES)            // 73728

__device__ __forceinline__ void load_split_tile(
    uint32_t sm_hi, uint32_t sm_lo,
    const unsigned* __restrict__ src, int row0, int stride, int col0,
    int tid, int rows_valid)
{
    int r = tid >> 1;
    int h = (tid & 1) * 32;
    bool valid = r < rows_valid;
    const uint4* p4 = (const uint4*)(src + (size_t)(row0 + r) * stride + col0 + h);
    #pragma unroll
    for (int u = 0; u < 8; u++) {
        uint4 w = valid ? p4[u] : make_uint4(0u, 0u, 0u, 0u);
        unsigned h01 = __byte_perm(w.x, w.y, 0x5410);   // hi bf16 pair
        unsigned h23 = __byte_perm(w.z, w.w, 0x5410);
        unsigned l01 = __byte_perm(w.x, w.y, 0x7632);   // lo bf16 pair
        unsigned l23 = __byte_perm(w.z, w.w, 0x7632);
        uint32_t off = (uint32_t)(r * SA_STRIDE + (h + u * 4) * 2);
        asm volatile("st.shared.v2.b32 [%0], {%1,%2};"
                     :: "r"(sm_hi + off), "r"(h01), "r"(h23) : "memory");
        asm volatile("st.shared.v2.b32 [%0], {%1,%2};"
                     :: "r"(sm_lo + off), "r"(l01), "r"(l23) : "memory");
    }
}

__global__ void __launch_bounds__(256, 2) k_gemm(int src, int layer,
                                                 const float* __restrict__ bias) {
    extern __shared__ char smem[];
    uint32_t sAh = smem_to_u32(smem);
    uint32_t sAl = sAh + TILE_BYTES;
    uint32_t sBh = sAh + 2 * TILE_BYTES;
    uint32_t sBl = sAh + 3 * TILE_BYTES;

    const int tid  = threadIdx.x;
    const int lane = tid & 31;
    const int wid  = tid >> 5;
    const int wm   = wid >> 1;       // 0..3  (m: 32 rows each)
    const int wn   = wid & 1;        // 0..1  (n: 64 cols each)
    const int row0 = blockIdx.x * 128;
    const unsigned* hsrc = pickP(src);
    const unsigned* wsrc = g_WtP + layer * (H * 256);

    int arows = NN - row0;
    if (arows > 128) arows = 128;

    float acc[2][8][4];
    #pragma unroll
    for (int i = 0; i < 2; i++)
        #pragma unroll
        for (int j = 0; j < 8; j++)
            #pragma unroll
            for (int q = 0; q < 4; q++) acc[i][j][q] = 0.f;

    const int lrow = lane & 15;
    const int lchk = lane >> 4;

    for (int c = 0; c < 4; c++) {
        const unsigned* asrc = (c < 2) ? (const unsigned*)g_aggP : hsrc;
        int acol = (c & 1) * 64;
        load_split_tile(sAh, sAl, asrc, row0, 128, acol, tid, arows);
        load_split_tile(sBh, sBl, wsrc, 0, 256, c * 64, tid, 128);
        __syncthreads();

        #pragma unroll
        for (int ks = 0; ks < 4; ks++) {
            uint32_t Ah[2][4], Al[2][4];
            #pragma unroll
            for (int im = 0; im < 2; im++) {
                uint32_t aoff = (uint32_t)((wm * 32 + im * 16 + lrow) * SA_STRIDE
                                           + (ks * 16 + lchk * 8) * 2);
                ldm_x4(Ah[im], sAh + aoff);
                ldm_x4(Al[im], sAl + aoff);
            }
            uint32_t Bh[8][2], Bl[8][2];
            #pragma unroll
            for (int jn = 0; jn < 4; jn++) {
                uint32_t boff = (uint32_t)((wn * 64 + jn * 16 + lrow) * SA_STRIDE
                                           + (ks * 16 + lchk * 8) * 2);
                uint32_t t[4];
                ldm_x4(t, sBh + boff);
                Bh[2 * jn][0] = t[0]; Bh[2 * jn][1] = t[2];
                Bh[2 * jn + 1][0] = t[1]; Bh[2 * jn + 1][1] = t[3];
                ldm_x4(t, sBl + boff);
                Bl[2 * jn][0] = t[0]; Bl[2 * jn][1] = t[2];
                Bl[2 * jn + 1][0] = t[1]; Bl[2 * jn + 1][1] = t[3];
            }
            #pragma unroll
            for (int im = 0; im < 2; im++)
                #pragma unroll
                for (int j = 0; j < 8; j++)
                    mma_bf16(acc[im][j], Ah[im], Bh[j]);
            #pragma unroll
            for (int im = 0; im < 2; im++)
                #pragma unroll
                for (int j = 0; j < 8; j++)
                    mma_bf16(acc[im][j], Ah[im], Bl[j]);
            #pragma unroll
            for (int im = 0; im < 2; im++)
                #pragma unroll
                for (int j = 0; j < 8; j++)
                    mma_bf16(acc[im][j], Al[im], Bh[j]);
        }
        __syncthreads();
    }

    // epilogue: bias + leaky relu -> g_y (minimal proven form)
    const int lr  = lane >> 2;
    const int lc2 = (lane & 3) * 2;
    #pragma unroll
    for (int im = 0; im < 2; im++) {
        #pragma unroll
        for (int j = 0; j < 8; j++) {
            int n = wn * 64 + j * 8 + lc2;
            float b0 = bias[n], b1 = bias[n + 1];
            int m0 = row0 + wm * 32 + im * 16 + lr;
            if (m0 < NN) {
                float v0 = acc[im][j][0] + b0;
                float v1 = acc[im][j][1] + b1;
                v0 = (v0 >= 0.f) ? v0 : SLOPE * v0;
                v1 = (v1 >= 0.f) ? v1 : SLOPE * v1;
                *(float2*)&g_y[(size_t)m0 * H + n] = make_float2(v0, v1);
            }
            int m1 = m0 + 8;
            if (m1 < NN) {
                float v2 = acc[im][j][2] + b0;
                float v3 = acc[im][j][3] + b1;
                v2 = (v2 >= 0.f) ? v2 : SLOPE * v2;
                v3 = (v3 >= 0.f) ? v3 : SLOPE * v3;
                *(float2*)&g_y[(size_t)m1 * H + n] = make_float2(v2, v3);
            }
        }
    }
}

// ---------------- BN stats (+ fused bnprep in last block) -------------------
__global__ void k_stats(int l, const float* __restrict__ gamma,
                        const float* __restrict__ beta) {
    int t = threadIdx.x;            // 128 threads = columns
    int r0 = blockIdx.x * 250;      // 200 blocks x 250 rows
    float s = 0.f, q = 0.f;
    for (int r = 0; r < 250; r++) {
        float v = g_y[(size_t)(r0 + r) * H + t];
        s += v;
        q += v * v;
    }
    atomicAdd(&g_sum[l * H + t], s);
    atomicAdd(&g_sumsq[l * H + t], q);
    __threadfence();
    __shared__ int isLast;
    if (t == 0) {
        unsigned old = atomicInc(&g_scnt[l], 199u);   // wraps to 0 after last
        isLast = (old == 199u);
    }
    __syncthreads();
    if (isLast) {
        float sum = atomicAdd(&g_sum[l * H + t], 0.f);
        float ssq = atomicAdd(&g_sumsq[l * H + t], 0.f);
        float inv_n = 1.0f / (float)NN;
        float mu  = sum * inv_n;
        float var = ssq * inv_n - mu * mu;
        float sc  = rsqrtf(var + BN_EPS) * gamma[t];
        g_scale[t] = sc;
        g_shift[t] = beta[t] - mu * sc;
    }
}
// BN apply: g_y -> packed h buffer dst (intermediate layers),
//           or g_y -> fp32 dout only (final layer)
__global__ void k_bn(int dst, float* __restrict__ dout) {
    int i = blockIdx.x * blockDim.x + threadIdx.x;
    if (i < NN * 32) {
        int c = (i & 31) * 4;
        float4 v = ((const float4*)g_y)[i];
        v.x = v.x * g_scale[c + 0] + g_shift[c + 0];
        v.y = v.y * g_scale[c + 1] + g_shift[c + 1];
        v.z = v.z * g_scale[c + 2] + g_shift[c + 2];
        v.w = v.w * g_scale[c + 3] + g_shift[c + 3];
        if (dout) {
            ((float4*)dout)[i] = v;
        } else {
            uint4 p = make_uint4(pack_f32(v.x), pack_f32(v.y),
                                 pack_f32(v.z), pack_f32(v.w));
            ((uint4*)pickPw(dst))[i] = p;
        }
    }
}

// ---------------- launch ---------------------------------------------------
extern "C" void kernel_launch(void* const* d_in, const int* in_sizes, int n_in,
                              void* d_out, int out_size) {
    const float* x     = (const float*)d_in[0];
    const void*  ei    = d_in[1];
    const float* Wl    = (const float*)d_in[2];
    const float* bl    = (const float*)d_in[3];
    const float* Wr    = (const float*)d_in[4];
    const float* gamma = (const float*)d_in[5];
    const float* beta  = (const float*)d_in[6];
    float*       out   = (float*)d_out;

    cudaFuncSetAttribute(k_gemm, cudaFuncAttributeMaxDynamicSharedMemorySize, GEMM_SMEM);

    // input pack + CSR build + all-layer weight pack
    k_xprep    <<<(NN * H + 255) / 256, 256>>>(x);
    k_zero_deg <<<196, 256>>>(ei);
    k_hist     <<<(EE + 255) / 256, 256>>>(ei);
    k_scan1    <<<196, 256>>>();
    k_scan2    <<<1, 256>>>();
    k_scan3    <<<196, 256>>>();
    k_fill     <<<(EE + 255) / 256, 256>>>(ei);
    k_wprep_all<<<512, 256>>>(Wl, Wr);

    // l0: xP->A, l1: A->B, l2: B->A, l3: A -> d_out
    const int srcs[4] = {0, 1, 2, 1};
    const int dsts[4] = {1, 2, 1, 2};

    for (int l = 0; l < 4; l++) {
        k_agg  <<<(NN + 7) / 8, 256>>>(srcs[l]);
        k_gemm <<<(NN + 127) / 128, 256, GEMM_SMEM>>>(srcs[l], l, bl + l * H);
        k_stats<<<200, 128>>>(l, gamma + l * H, beta + l * H);
        k_bn   <<<(NN * 32 + 255) / 256, 256>>>(dsts[l], (l == 3) ? out : nullptr);
    }
}

// round 16
// speedup vs baseline: 1.0408x; 1.0140x over previous
#include <cuda_runtime.h>
#include <cuda_bf16.h>
#include <cstdint>

#define NN 50000
#define EE 800000
#define H  128
constexpr float BN_EPS = 1e-5f;
constexpr float SLOPE  = 0.01f;

// ---------------- scratch (device globals; no allocation allowed) ----------
// packed (bf16 hi | bf16 lo<<16) feature buffers
__device__ __align__(16) unsigned g_xP  [NN * H];
__device__ __align__(16) unsigned g_hA  [NN * H];
__device__ __align__(16) unsigned g_hB  [NN * H];
__device__ __align__(16) unsigned g_aggP[NN * H];
__device__ __align__(16) unsigned g_WtP [4 * H * 256];  // W^T packed, all layers
__device__ __align__(16) float    g_y   [NN * H];       // fp32 pre-BN activations
__device__ int      g_rowptr[NN + 1];
__device__ int      g_cursor[NN];
__device__ int      g_col[EE];
__device__ int      g_bsum[256];
__device__ int      g_boff[256];
__device__ float    g_sum[4 * H];
__device__ float    g_sumsq[4 * H];
__device__ float    g_scale[H];
__device__ float    g_shift[H];
__device__ unsigned g_scnt[4];
__device__ int      g_done[4];
__device__ int      g_is64;

// ---------------- helpers --------------------------------------------------
__device__ __forceinline__ const unsigned* pickP(int s) {
    return (s == 0) ? (const unsigned*)g_xP
         : (s == 1) ? (const unsigned*)g_hA : (const unsigned*)g_hB;
}
__device__ __forceinline__ unsigned* pickPw(int s) {
    return (s == 1) ? (unsigned*)g_hA : (unsigned*)g_hB;
}

__device__ __forceinline__ unsigned pack_f32(float v) {
    unsigned hb = (unsigned)__bfloat16_as_ushort(__float2bfloat16(v));
    float hf = __uint_as_float(hb << 16);
    float r = v - hf;
    unsigned lb = (unsigned)__bfloat16_as_ushort(__float2bfloat16(r));
    return hb | (lb << 16);
}
__device__ __forceinline__ float unpack_f32(unsigned p) {
    return __uint_as_float(p << 16) + __uint_as_float(p & 0xFFFF0000u);
}

__device__ __forceinline__ uint32_t smem_to_u32(const void* p) {
    uint32_t a;
    asm("{ .reg .u64 t; cvta.to.shared.u64 t, %1; cvt.u32.u64 %0, t; }"
        : "=r"(a) : "l"(p));
    return a;
}

// ldmatrix x4 (baseline PTX, legal on compute_103)
__device__ __forceinline__ void ldm_x4(uint32_t* f, uint32_t addr) {
    asm volatile("ldmatrix.sync.aligned.m8n8.x4.shared.b16 {%0,%1,%2,%3}, [%4];"
                 : "=r"(f[0]), "=r"(f[1]), "=r"(f[2]), "=r"(f[3]) : "r"(addr));
}
// mma m16n8k16 bf16 (baseline PTX, sm_80+)
__device__ __forceinline__ void mma_bf16(float* c, const uint32_t* a, const uint32_t* b) {
    asm volatile("mma.sync.aligned.m16n8k16.row.col.f32.bf16.bf16.f32 "
                 "{%0,%1,%2,%3}, {%4,%5,%6,%7}, {%8,%9}, {%0,%1,%2,%3};"
                 : "+f"(c[0]), "+f"(c[1]), "+f"(c[2]), "+f"(c[3])
                 : "r"(a[0]), "r"(a[1]), "r"(a[2]), "r"(a[3]),
                   "r"(b[0]), "r"(b[1]));
}

// edge accessors honoring detected dtype
__device__ __forceinline__ int edge_src(const void* ei, int e) {
    if (g_is64) return (int)((const long long*)ei)[e];
    return ((const int*)ei)[e];
}
__device__ __forceinline__ int edge_dst(const void* ei, int e) {
    if (g_is64) return (int)((const long long*)ei)[EE + e];
    return ((const int*)ei)[EE + e];
}

// ---------------- CSR build ------------------------------------------------
// block 0 additionally probes the edge dtype (int64 vs int32)
__global__ void k_zero_deg(const void* ei) {
    int i = blockIdx.x * blockDim.x + threadIdx.x;
    if (i < NN) g_cursor[i] = 0;
    if (blockIdx.x == 0) {
        __shared__ int bad;
        if (threadIdx.x == 0) bad = 0;
        __syncthreads();
        long long v = ((const long long*)ei)[threadIdx.x];
        if (v < 0 || v >= NN) atomicOr(&bad, 1);
        __syncthreads();
        if (threadIdx.x == 0) g_is64 = bad ? 0 : 1;
    }
}
__global__ void k_hist(const void* __restrict__ ei) {
    int e = blockIdx.x * blockDim.x + threadIdx.x;
    if (e < EE) atomicAdd(&g_cursor[edge_dst(ei, e)], 1);
}
__global__ void k_scan1() {
    __shared__ int s[256];
    int t = threadIdx.x, i = blockIdx.x * 256 + t;
    int d = (i < NN) ? g_cursor[i] : 0;
    s[t] = d;
    __syncthreads();
    for (int off = 1; off < 256; off <<= 1) {
        int add = (t >= off) ? s[t - off] : 0;
        __syncthreads();
        s[t] += add;
        __syncthreads();
    }
    if (i < NN) g_rowptr[i] = s[t] - d;
    if (t == 255) g_bsum[blockIdx.x] = s[255];
}
__global__ void k_scan2() {
    __shared__ int s[256];
    int t = threadIdx.x;
    int d = (t < 196) ? g_bsum[t] : 0;
    s[t] = d;
    __syncthreads();
    for (int off = 1; off < 256; off <<= 1) {
        int add = (t >= off) ? s[t - off] : 0;
        __syncthreads();
        s[t] += add;
        __syncthreads();
    }
    if (t < 196) g_boff[t] = s[t] - d;
}
__global__ void k_scan3() {
    int i = blockIdx.x * 256 + threadIdx.x;
    if (i < NN) {
        int v = g_rowptr[i] + g_boff[blockIdx.x];
        g_rowptr[i] = v;
        g_cursor[i] = v;
    }
    if (i == 0) g_rowptr[NN] = EE;
}
__global__ void k_fill(const void* __restrict__ ei) {
    int e = blockIdx.x * blockDim.x + threadIdx.x;
    if (e < EE) {
        int src = edge_src(ei, e);
        int pos = atomicAdd(&g_cursor[edge_dst(ei, e)], 1);
        g_col[pos] = src;
    }
}

// ---------------- input / weight packing -----------------------------------
__global__ void k_xprep(const float* __restrict__ x) {
    int i = blockIdx.x * blockDim.x + threadIdx.x;
    if (i < NN * H) g_xP[i] = pack_f32(x[i]);
}
// ALL layers' W^T packed upfront (B[n][k] = Wcat[k][n]); zeroes BN state
__global__ void k_wprep_all(const float* __restrict__ Wl,
                            const float* __restrict__ Wr) {
    int b = blockIdx.x;              // 0..511
    int l = b >> 7;                  // layer 0..3
    int idx = (b & 127) * 256 + threadIdx.x;   // 0..32767
    int n = idx >> 8, k = idx & 255;
    const float* wl = Wl + l * H * H;
    const float* wr = Wr + l * H * H;
    float w = (k < H) ? wl[k * H + n] : wr[(k - H) * H + n];
    g_WtP[l * (H * 256) + n * 256 + k] = pack_f32(w);
    if ((b & 127) == 0 && threadIdx.x < H) {
        g_sum[l * H + threadIdx.x]   = 0.f;
        g_sumsq[l * H + threadIdx.x] = 0.f;
        if (b == 0 && threadIdx.x < 4) {
            g_scnt[threadIdx.x] = 0u;
            g_done[threadIdx.x] = 0;
        }
    }
}

// ---------------- aggregation: one warp per node, 4-wide edge unroll -------
__global__ void __launch_bounds__(256) k_agg(int src) {
    int warp = threadIdx.x >> 5;
    int lane = threadIdx.x & 31;
    int node = blockIdx.x * 8 + warp;
    if (node >= NN) return;
    const uint4* in4 = (const uint4*)pickP(src);
    int beg = g_rowptr[node];
    int end = g_rowptr[node + 1];
    float4 a = make_float4(0.f, 0.f, 0.f, 0.f);
    int j = beg;
    for (; j + 3 < end; j += 4) {
        int s0 = g_col[j + 0], s1 = g_col[j + 1];
        int s2 = g_col[j + 2], s3 = g_col[j + 3];
        uint4 w0 = in4[s0 * 32 + lane];
        uint4 w1 = in4[s1 * 32 + lane];
        uint4 w2 = in4[s2 * 32 + lane];
        uint4 w3 = in4[s3 * 32 + lane];
        a.x += (unpack_f32(w0.x) + unpack_f32(w1.x)) + (unpack_f32(w2.x) + unpack_f32(w3.x));
        a.y += (unpack_f32(w0.y) + unpack_f32(w1.y)) + (unpack_f32(w2.y) + unpack_f32(w3.y));
        a.z += (unpack_f32(w0.z) + unpack_f32(w1.z)) + (unpack_f32(w2.z) + unpack_f32(w3.z));
        a.w += (unpack_f32(w0.w) + unpack_f32(w1.w)) + (unpack_f32(w2.w) + unpack_f32(w3.w));
    }
    for (; j < end; j++) {
        uint4 w0 = in4[g_col[j] * 32 + lane];
        a.x += unpack_f32(w0.x); a.y += unpack_f32(w0.y);
        a.z += unpack_f32(w0.z); a.w += unpack_f32(w0.w);
    }
    float inv = 1.0f / (float)max(end - beg, 1);
    uint4 o = make_uint4(pack_f32(a.x * inv), pack_f32(a.y * inv),
                         pack_f32(a.z * inv), pack_f32(a.w * inv));
    ((uint4*)g_aggP)[node * 32 + lane] = o;
}

// ---------------- tensor-core GEMM (mma.sync bf16, 3-term split) -----------
// D[128,128] fp32 = sum over K=256 of Ah@Bh + Ah@Bl + Al@Bh
// A = [agg | h], B = W^T[n][k] (per-layer slice). Epilogue -> g_y (fp32).
// smem tiles: 128 rows x 64 bf16, row stride 144B (ldmatrix conflict-free).
// __launch_bounds__(256,2): 2 CTAs/SM (proven round 13). Epilogue minimal —
// every attempted addition (stats atomics, packing) has measurably regressed.
#define SA_STRIDE 144
#define TILE_BYTES (128 * SA_STRIDE)           // 18432
#define GEMM_SMEM  (4 * TILE_BYTES)            // 73728

__device__ __forceinline__ void load_split_tile(
    uint32_t sm_hi, uint32_t sm_lo,
    const unsigned* __restrict__ src, int row0, int stride, int col0,
    int tid, int rows_valid)
{
    int r = tid >> 1;
    int h = (tid & 1) * 32;
    bool valid = r < rows_valid;
    const uint4* p4 = (const uint4*)(src + (size_t)(row0 + r) * stride + col0 + h);
    #pragma unroll
    for (int u = 0; u < 8; u++) {
        uint4 w = valid ? p4[u] : make_uint4(0u, 0u, 0u, 0u);
        unsigned h01 = __byte_perm(w.x, w.y, 0x5410);   // hi bf16 pair
        unsigned h23 = __byte_perm(w.z, w.w, 0x5410);
        unsigned l01 = __byte_perm(w.x, w.y, 0x7632);   // lo bf16 pair
        unsigned l23 = __byte_perm(w.z, w.w, 0x7632);
        uint32_t off = (uint32_t)(r * SA_STRIDE + (h + u * 4) * 2);
        asm volatile("st.shared.v2.b32 [%0], {%1,%2};"
                     :: "r"(sm_hi + off), "r"(h01), "r"(h23) : "memory");
        asm volatile("st.shared.v2.b32 [%0], {%1,%2};"
                     :: "r"(sm_lo + off), "r"(l01), "r"(l23) : "memory");
    }
}

__global__ void __launch_bounds__(256, 2) k_gemm(int src, int layer,
                                                 const float* __restrict__ bias) {
    extern __shared__ char smem[];
    uint32_t sAh = smem_to_u32(smem);
    uint32_t sAl = sAh + TILE_BYTES;
    uint32_t sBh = sAh + 2 * TILE_BYTES;
    uint32_t sBl = sAh + 3 * TILE_BYTES;

    const int tid  = threadIdx.x;
    const int lane = tid & 31;
    const int wid  = tid >> 5;
    const int wm   = wid >> 1;       // 0..3  (m: 32 rows each)
    const int wn   = wid & 1;        // 0..1  (n: 64 cols each)
    const int row0 = blockIdx.x * 128;
    const unsigned* hsrc = pickP(src);
    const unsigned* wsrc = g_WtP + layer * (H * 256);

    int arows = NN - row0;
    if (arows > 128) arows = 128;

    float acc[2][8][4];
    #pragma unroll
    for (int i = 0; i < 2; i++)
        #pragma unroll
        for (int j = 0; j < 8; j++)
            #pragma unroll
            for (int q = 0; q < 4; q++) acc[i][j][q] = 0.f;

    const int lrow = lane & 15;
    const int lchk = lane >> 4;

    for (int c = 0; c < 4; c++) {
        const unsigned* asrc = (c < 2) ? (const unsigned*)g_aggP : hsrc;
        int acol = (c & 1) * 64;
        load_split_tile(sAh, sAl, asrc, row0, 128, acol, tid, arows);
        load_split_tile(sBh, sBl, wsrc, 0, 256, c * 64, tid, 128);
        __syncthreads();

        #pragma unroll
        for (int ks = 0; ks < 4; ks++) {
            uint32_t Ah[2][4], Al[2][4];
            #pragma unroll
            for (int im = 0; im < 2; im++) {
                uint32_t aoff = (uint32_t)((wm * 32 + im * 16 + lrow) * SA_STRIDE
                                           + (ks * 16 + lchk * 8) * 2);
                ldm_x4(Ah[im], sAh + aoff);
                ldm_x4(Al[im], sAl + aoff);
            }
            uint32_t Bh[8][2], Bl[8][2];
            #pragma unroll
            for (int jn = 0; jn < 4; jn++) {
                uint32_t boff = (uint32_t)((wn * 64 + jn * 16 + lrow) * SA_STRIDE
                                           + (ks * 16 + lchk * 8) * 2);
                uint32_t t[4];
                ldm_x4(t, sBh + boff);
                Bh[2 * jn][0] = t[0]; Bh[2 * jn][1] = t[2];
                Bh[2 * jn + 1][0] = t[1]; Bh[2 * jn + 1][1] = t[3];
                ldm_x4(t, sBl + boff);
                Bl[2 * jn][0] = t[0]; Bl[2 * jn][1] = t[2];
                Bl[2 * jn + 1][0] = t[1]; Bl[2 * jn + 1][1] = t[3];
            }
            #pragma unroll
            for (int im = 0; im < 2; im++)
                #pragma unroll
                for (int j = 0; j < 8; j++)
                    mma_bf16(acc[im][j], Ah[im], Bh[j]);
            #pragma unroll
            for (int im = 0; im < 2; im++)
                #pragma unroll
                for (int j = 0; j < 8; j++)
                    mma_bf16(acc[im][j], Ah[im], Bl[j]);
            #pragma unroll
            for (int im = 0; im < 2; im++)
                #pragma unroll
                for (int j = 0; j < 8; j++)
                    mma_bf16(acc[im][j], Al[im], Bh[j]);
        }
        __syncthreads();
    }

    // epilogue: bias + leaky relu -> g_y (minimal proven form)
    const int lr  = lane >> 2;
    const int lc2 = (lane & 3) * 2;
    #pragma unroll
    for (int im = 0; im < 2; im++) {
        #pragma unroll
        for (int j = 0; j < 8; j++) {
            int n = wn * 64 + j * 8 + lc2;
            float b0 = bias[n], b1 = bias[n + 1];
            int m0 = row0 + wm * 32 + im * 16 + lr;
            if (m0 < NN) {
                float v0 = acc[im][j][0] + b0;
                float v1 = acc[im][j][1] + b1;
                v0 = (v0 >= 0.f) ? v0 : SLOPE * v0;
                v1 = (v1 >= 0.f) ? v1 : SLOPE * v1;
                *(float2*)&g_y[(size_t)m0 * H + n] = make_float2(v0, v1);
            }
            int m1 = m0 + 8;
            if (m1 < NN) {
                float v2 = acc[im][j][2] + b0;
                float v3 = acc[im][j][3] + b1;
                v2 = (v2 >= 0.f) ? v2 : SLOPE * v2;
                v3 = (v3 >= 0.f) ? v3 : SLOPE * v3;
                *(float2*)&g_y[(size_t)m1 * H + n] = make_float2(v2, v3);
            }
        }
    }
}

// ---------------- fused BN stats + prep + apply (single kernel) -------------
// 400 blocks x 128 threads; 125 rows per block. Phase 1: partial sums ->
// global atomics; last-arriving block computes scale/shift, fences, sets
// g_done[l]. Other blocks spin (all 400 blocks co-resident: no deadlock).
// Phase 2: every block applies BN to its own (L2-hot) slice.
__global__ void __launch_bounds__(128) k_statsbn(
    int l, const float* __restrict__ gamma, const float* __restrict__ beta,
    int dst, float* __restrict__ dout)
{
    int t = threadIdx.x;            // column
    int r0 = blockIdx.x * 125;
    float s = 0.f, q = 0.f;
    for (int r = 0; r < 125; r++) {
        float v = g_y[(size_t)(r0 + r) * H + t];
        s += v;
        q += v * v;
    }
    atomicAdd(&g_sum[l * H + t], s);
    atomicAdd(&g_sumsq[l * H + t], q);
    __threadfence();

    __shared__ int isLast;
    if (t == 0) {
        unsigned old = atomicInc(&g_scnt[l], 399u);   // wraps to 0 after last
        isLast = (old == 399u);
    }
    __syncthreads();
    if (isLast) {
        float sum = atomicAdd(&g_sum[l * H + t], 0.f);
        float ssq = atomicAdd(&g_sumsq[l * H + t], 0.f);
        float inv_n = 1.0f / (float)NN;
        float mu  = sum * inv_n;
        float var = ssq * inv_n - mu * mu;
        float sc  = rsqrtf(var + BN_EPS) * gamma[t];
        g_scale[t] = sc;
        g_shift[t] = beta[t] - mu * sc;
        __threadfence();
        __syncthreads();
        if (t == 0) atomicExch(&g_done[l], 1);
    } else {
        if (t == 0) {
            while (atomicAdd(&g_done[l], 0) == 0) __nanosleep(200);
        }
        __syncthreads();
    }

    // scale/shift to smem (first global read this launch: L1 cold -> fresh L2)
    __shared__ float s_sc[H], s_sh[H];
    s_sc[t] = g_scale[t];
    s_sh[t] = g_shift[t];
    __syncthreads();

    // phase 2: apply BN to this block's slice (float4-vectorized)
    const int base = blockIdx.x * 125 * 32;       // float4 index base
    if (dout) {
        for (int idx = t; idx < 125 * 32; idx += 128) {
            int i = base + idx;
            int c = (idx & 31) * 4;
            float4 v = ((const float4*)g_y)[i];
            v.x = v.x * s_sc[c + 0] + s_sh[c + 0];
            v.y = v.y * s_sc[c + 1] + s_sh[c + 1];
            v.z = v.z * s_sc[c + 2] + s_sh[c + 2];
            v.w = v.w * s_sc[c + 3] + s_sh[c + 3];
            ((float4*)dout)[i] = v;
        }
    } else {
        unsigned* outp = pickPw(dst);
        for (int idx = t; idx < 125 * 32; idx += 128) {
            int i = base + idx;
            int c = (idx & 31) * 4;
            float4 v = ((const float4*)g_y)[i];
            v.x = v.x * s_sc[c + 0] + s_sh[c + 0];
            v.y = v.y * s_sc[c + 1] + s_sh[c + 1];
            v.z = v.z * s_sc[c + 2] + s_sh[c + 2];
            v.w = v.w * s_sc[c + 3] + s_sh[c + 3];
            uint4 p = make_uint4(pack_f32(v.x), pack_f32(v.y),
                                 pack_f32(v.z), pack_f32(v.w));
            ((uint4*)outp)[i] = p;
        }
    }
}

// ---------------- launch ---------------------------------------------------
extern "C" void kernel_launch(void* const* d_in, const int* in_sizes, int n_in,
                              void* d_out, int out_size) {
    const float* x     = (const float*)d_in[0];
    const void*  ei    = d_in[1];
    const float* Wl    = (const float*)d_in[2];
    const float* bl    = (const float*)d_in[3];
    const float* Wr    = (const float*)d_in[4];
    const float* gamma = (const float*)d_in[5];
    const float* beta  = (const float*)d_in[6];
    float*       out   = (float*)d_out;

    cudaFuncSetAttribute(k_gemm, cudaFuncAttributeMaxDynamicSharedMemorySize, GEMM_SMEM);

    // input pack + CSR build + all-layer weight pack
    k_xprep    <<<(NN * H + 255) / 256, 256>>>(x);
    k_zero_deg <<<196, 256>>>(ei);
    k_hist     <<<(EE + 255) / 256, 256>>>(ei);
    k_scan1    <<<196, 256>>>();
    k_scan2    <<<1, 256>>>();
    k_scan3    <<<196, 256>>>();
    k_fill     <<<(EE + 255) / 256, 256>>>(ei);
    k_wprep_all<<<512, 256>>>(Wl, Wr);

    // l0: xP->A, l1: A->B, l2: B->A, l3: A -> d_out
    const int srcs[4] = {0, 1, 2, 1};
    const int dsts[4] = {1, 2, 1, 2};

    for (int l = 0; l < 4; l++) {
        k_agg    <<<(NN + 7) / 8, 256>>>(srcs[l]);
        k_gemm   <<<(NN + 127) / 128, 256, GEMM_SMEM>>>(srcs[l], l, bl + l * H);
        k_statsbn<<<400, 128>>>(l, gamma + l * H, beta + l * H,
                                dsts[l], (l == 3) ? out : nullptr);
    }
}